// round 13
// baseline (speedup 1.0000x reference)
#include <cuda_runtime.h>
#include <math.h>
#include <stdint.h>

__device__ int g_tile_counter;   // reset to 0 by kernel_launch each call

namespace {

constexpr int Bc = 32, Nc = 96, Dc = 32, Fc = 16;
constexpr int THREADS = 640;        // five independent 128-thread streams
constexpr int SWIDTH  = 128;
constexpr int NSTREAM = 5;
constexpr int GRID    = 152;        // persistent: 1 CTA per SM
constexpr int NTILES  = Bc * Nc;    // 3072
constexpr int NSTREAMS_TOTAL = GRID * NSTREAM;   // 760
constexpr int EPAD    = 20;

// Shared (read-only after init)
constexpr int OFF_WFRAG = 0;                 // float4[128 nt][32 lane] = 65536
constexpr int OFF_BIAS  = 65536;             // 1024 f = 4096
constexpr int OFF_WIH   = 69632;             // w_ih^T [32][96] = 12288
constexpr int OFF_WHH   = 81920;             // w_hh^T [32][96] = 12288
// Per-stream block
constexpr int OFF_S0  = 94208;
constexpr int SO_E    = 0;       // 96 x 20 u32 = 7680
constexpr int SO_MN   = 7680;    // 1536 float2 = 12288
constexpr int SO_ACT  = 19968;   // [2][96] int = 768   (parity double-buffer)
constexpr int SO_X1   = 20736;   // [2][32] f = 256
constexpr int SO_META = 20992;   // cnt[2], tile[2] = 16, pad 32
constexpr int SO_AGG  = 21024;   // [2][32] f = 256
constexpr int SO_GI   = 21280;   // 96 f
constexpr int SO_GH   = 21664;   // 96 f
constexpr int SO_H1   = 22048;   // 32 f
constexpr int S_BYTES = 22272;
constexpr int SMEM_BYTES = OFF_S0 + NSTREAM * S_BYTES;   // 205568

__device__ __forceinline__ float sigmoidf_(float x) { return 1.0f / (1.0f + expf(-x)); }

__device__ __forceinline__ uint32_t f2tf32(float x) {
    uint32_t r;
    asm("cvt.rna.tf32.f32 %0, %1;" : "=r"(r) : "f"(x));
    return r;
}

__device__ __forceinline__ void mma_tf32(float& d0, float& d1, float& d2, float& d3,
                                         uint32_t a0, uint32_t a1, uint32_t a2, uint32_t a3,
                                         uint32_t b0, uint32_t b1) {
    asm volatile(
        "mma.sync.aligned.m16n8k8.row.col.f32.tf32.tf32.f32 "
        "{%0,%1,%2,%3}, {%4,%5,%6,%7}, {%8,%9}, {%0,%1,%2,%3};"
        : "+f"(d0), "+f"(d1), "+f"(d2), "+f"(d3)
        : "r"(a0), "r"(a1), "r"(a2), "r"(a3), "r"(b0), "r"(b1));
}

// mn storage: (e,qp) -> float2 slot = ((qp>>2)*12 + (e>>3))*32 + (qp&3)*8 + (e&7)
__device__ __forceinline__ int mn_idx(int e, int qp) {
    return (((qp >> 2) * 12 + (e >> 3)) << 5) + ((qp & 3) << 3) + (e & 7);
}

__device__ __forceinline__ void stream_bar(int s) {
    asm volatile("bar.sync %0, %1;" :: "r"(s + 1), "r"(SWIDTH) : "memory");
}

// Warp-collective: compact active edges of tile t into slot p; stage x1.
__device__ __forceinline__ void compact_tile(int t, int p, int lane,
                                             const float* __restrict__ mask,
                                             const float* __restrict__ nodes,
                                             int* act_sh, int* cnt_sh, float* x1_sh) {
    const int b = t / Nc;
    const int i = t - b * Nc;
    const size_t mbase = (size_t)b * (Nc * Nc) + (size_t)i * Nc;
    int cnt = 0;
#pragma unroll
    for (int rr = 0; rr < Nc / 32; rr++) {
        const int j = rr * 32 + lane;
        const bool a = (mask[mbase + j] != 0.0f);
        const unsigned bal = __ballot_sync(0xffffffffu, a);
        if (a) act_sh[p * 96 + cnt + __popc(bal & ((1u << lane) - 1u))] = j;
        cnt += __popc(bal);
    }
    if (lane == 0) cnt_sh[p] = cnt;
    x1_sh[p * 32 + lane] = nodes[((size_t)b * Nc + i) * Dc + lane];
}

// Warp-collective GRU for one tile (warp 3 of each stream only).
__device__ __forceinline__ void gru_tile(int ptile, int lane,
                                         const float* x1p, const float* aggp,
                                         float* gi_sh, float* gh_sh, float* h1_sh,
                                         const float* wihT, const float* whhT,
                                         const float* __restrict__ b_ih,
                                         const float* __restrict__ b_hh,
                                         float* __restrict__ out) {
    const int pb = ptile / Nc;
    const int pi = ptile - pb * Nc;
#pragma unroll
    for (int g3 = 0; g3 < 3; g3++) {
        const int gate = g3 * 32 + lane;
        float g = b_ih[gate];
#pragma unroll
        for (int d = 0; d < Dc; d++) g = fmaf(x1p[d], wihT[d * 96 + gate], g);
        gi_sh[gate] = g;
    }
    __syncwarp();
    {
        const float r = sigmoidf_(gi_sh[lane] + b_hh[lane]);
        const float z = sigmoidf_(gi_sh[32 + lane] + b_hh[32 + lane]);
        const float n = tanhf(gi_sh[64 + lane] + r * b_hh[64 + lane]);
        h1_sh[lane] = (1.0f - z) * n;   // + z*h0, h0 = 0
    }
    __syncwarp();
#pragma unroll
    for (int g3 = 0; g3 < 3; g3++) {
        const int gate = g3 * 32 + lane;
        float g  = b_ih[gate];
        float gh = b_hh[gate];
#pragma unroll
        for (int d = 0; d < Dc; d++) {
            g  = fmaf(aggp[d],  wihT[d * 96 + gate], g);
            gh = fmaf(h1_sh[d], whhT[d * 96 + gate], gh);
        }
        gi_sh[gate] = g;
        gh_sh[gate] = gh;
    }
    __syncwarp();
    {
        const float r = sigmoidf_(gi_sh[lane] + gh_sh[lane]);
        const float z = sigmoidf_(gi_sh[32 + lane] + gh_sh[32 + lane]);
        const float n = tanhf(gi_sh[64 + lane] + r * gh_sh[64 + lane]);
        out[((size_t)pb * Nc + pi) * Dc + lane] = (1.0f - z) * n + z * h1_sh[lane];
    }
}

__global__ __launch_bounds__(THREADS, 1)
void mp_layer_kernel(const float* __restrict__ nodes,   // [B, N, D]
                     const float* __restrict__ edges,   // [B, N*N, F]
                     const float* __restrict__ mask,    // [B, N*N, 1] (0/1)
                     const float* __restrict__ W_agg,   // [F, D*D]
                     const float* __restrict__ b_agg,   // [D*D]
                     const float* __restrict__ w_ih,    // [3D, D]
                     const float* __restrict__ w_hh,    // [3D, D]
                     const float* __restrict__ b_ih,    // [3D]
                     const float* __restrict__ b_hh,    // [3D]
                     float* __restrict__ out)           // [B, N, D]
{
    extern __shared__ char smem[];
    float4* wfrag4  = reinterpret_cast<float4*>(smem + OFF_WFRAG);
    float*  bias_sh = reinterpret_cast<float*>(smem + OFF_BIAS);
    float*  wihT    = reinterpret_cast<float*>(smem + OFF_WIH);
    float*  whhT    = reinterpret_cast<float*>(smem + OFF_WHH);

    const int tid = threadIdx.x;

    // ---- One-time per CTA: W fragments (tf32, both k-steps packed), bias,
    //      transposed GRU weights ----
    for (int idx = tid; idx < 128 * 32; idx += THREADS) {
        const int l  = idx & 31;
        const int nt = idx >> 5;
        const int col = nt * 8 + (l >> 2);
        const int k   = l & 3;
        float4 v;
        v.x = __uint_as_float(f2tf32(W_agg[(k)      * 1024 + col]));
        v.y = __uint_as_float(f2tf32(W_agg[(k + 4)  * 1024 + col]));
        v.z = __uint_as_float(f2tf32(W_agg[(k + 8)  * 1024 + col]));
        v.w = __uint_as_float(f2tf32(W_agg[(k + 12) * 1024 + col]));
        wfrag4[idx] = v;
    }
    for (int c = tid; c < 1024; c += THREADS) bias_sh[c] = b_agg[c];
    for (int idx = tid; idx < 96 * 32; idx += THREADS) {
        const int g = idx >> 5;
        const int d = idx & 31;
        wihT[d * 96 + g] = w_ih[idx];
        whhT[d * 96 + g] = w_hh[idx];
    }
    __syncthreads();

    // ---- Stream-local views ----
    const int s    = tid >> 7;          // stream 0..4
    const int tids = tid & (SWIDTH - 1);
    const int lane = tid & 31;
    const int wq   = (tid >> 5) & 3;

    char* sbase = smem + OFF_S0 + s * S_BYTES;
    uint32_t* E_sh   = reinterpret_cast<uint32_t*>(sbase + SO_E);
    float2*   mnS    = reinterpret_cast<float2*>(sbase + SO_MN);
    int*      act_sh = reinterpret_cast<int*>(sbase + SO_ACT);
    float*    x1_sh  = reinterpret_cast<float*>(sbase + SO_X1);
    int*      cnt_sh = reinterpret_cast<int*>(sbase + SO_META);
    int*      tile_sh= reinterpret_cast<int*>(sbase + SO_META) + 2;
    float*    agg_sh = reinterpret_cast<float*>(sbase + SO_AGG);
    float*    gi_sh  = reinterpret_cast<float*>(sbase + SO_GI);
    float*    gh_sh  = reinterpret_cast<float*>(sbase + SO_GH);
    float*    h1_sh  = reinterpret_cast<float*>(sbase + SO_H1);

    const int gsid = blockIdx.x * NSTREAM + s;

    // ---- Prefetch: warp 3 compacts the stream's static first tile ----
    if (wq == 3) {
        if (lane == 0) tile_sh[0] = gsid;
        compact_tile(gsid, 0, lane, mask, nodes, act_sh, cnt_sh, x1_sh);
    }
    stream_bar(s);

    // Lane constants for the mainloop
    const int l4   = lane & 3;
    const int lr   = lane >> 2;
    const int mnlo = (l4 << 3) + (lr & 7);
    const int lrh  = lr >> 3;

    // ---- Dynamic pipelined tile loop ----
    int it = 0;
    while (true) {
        const int par = it & 1;
        const int cur = tile_sh[par];
        if (cur >= NTILES) break;                 // stream-uniform

        const int b = cur / Nc;
        const int i = cur - b * Nc;
        const size_t ebase = ((size_t)b * (Nc * Nc) + (size_t)i * Nc) * Fc;
        const size_t nbase = (size_t)b * (Nc * Dc);
        const int cnt    = cnt_sh[par];
        const int mtiles = (cnt + 15) >> 4;
        const int padcnt = mtiles << 4;

        if (wq < 3) {
            // Warps 0-2: stage E_act (tf32, float4-vectorized) and mn.
            const int* act = act_sh + par * 96;
            for (int idx = tids; idx < padcnt * 4; idx += 96) {
                const int a  = idx >> 2;
                const int f4 = (idx & 3) << 2;
                uint4 o = make_uint4(0u, 0u, 0u, 0u);
                if (a < cnt) {
                    const float4 v = *reinterpret_cast<const float4*>(
                        edges + ebase + (size_t)act[a] * Fc + f4);
                    o.x = f2tf32(v.x); o.y = f2tf32(v.y);
                    o.z = f2tf32(v.z); o.w = f2tf32(v.w);
                }
                *reinterpret_cast<uint4*>(E_sh + a * EPAD + f4) = o;
            }
            for (int idx = tids; idx < padcnt * 8; idx += 96) {
                const int a  = idx >> 3;
                const int q2 = (idx & 7) << 1;    // qp pair: q2, q2+1
                float4 v = make_float4(0.f, 0.f, 0.f, 0.f);
                if (a < cnt) {
                    v = *reinterpret_cast<const float4*>(
                        nodes + nbase + (size_t)act[a] * Dc + q2 * 2);
                }
                mnS[mn_idx(a, q2)]     = make_float2(v.x, v.y);
                mnS[mn_idx(a, q2 + 1)] = make_float2(v.z, v.w);
            }
        } else {
            // Warp 3: GRU(previous tile), then grab + compact next.
            if (it > 0) {
                const int pp = (it - 1) & 1;
                gru_tile(tile_sh[pp], lane, x1_sh + pp * 32, agg_sh + pp * 32,
                         gi_sh, gh_sh, h1_sh, wihT, whhT, b_ih, b_hh, out);
            }
            int nxt;
            if (lane == 0) nxt = NSTREAMS_TOTAL + atomicAdd(&g_tile_counter, 1);
            nxt = __shfl_sync(0xffffffffu, nxt, 0);
            const int np = (it + 1) & 1;
            if (lane == 0) tile_sh[np] = nxt;
            if (nxt < NTILES)
                compact_tile(nxt, np, lane, mask, nodes, act_sh, cnt_sh, x1_sh);
        }
        stream_bar(s);   // staging done, GRU done, next tile compacted

        // ---- MMA + fused epilogue (all 4 warps); single m-block loop,
        //      c-outer ordering, pointer strength-reduction ----
        float acc[8] = {0.f, 0.f, 0.f, 0.f, 0.f, 0.f, 0.f, 0.f};

        for (int mt = 0; mt < mtiles; mt++) {
            const int r0 = mt * 16 + lr;
            const uint32_t* e0p = E_sh + r0 * EPAD;
            const uint32_t a00 = e0p[l4],      a01 = e0p[8*EPAD + l4];
            const uint32_t a02 = e0p[l4 + 4],  a03 = e0p[8*EPAD + l4 + 4];
            const uint32_t a10 = e0p[l4 + 8],  a11 = e0p[8*EPAD + l4 + 8];
            const uint32_t a12 = e0p[l4 + 12], a13 = e0p[8*EPAD + l4 + 12];
            const int blk0 = mt * 2 + lrh;

#pragma unroll
            for (int c = 0; c < 4; c++) {
                const float2* mp = mnS + ((c * 12 + blk0) << 5) + mnlo;
                const float2 m0 = mp[0];
                const float2 m1 = mp[32];
                const float4* wp = wfrag4 + (wq * 32 + c) * 32 + lane;
                const float2* bp = reinterpret_cast<const float2*>(
                    bias_sh + wq * 256 + c * 8 + l4 * 2);
#pragma unroll
                for (int tsub = 0; tsub < 8; tsub++) {
                    const float4 bf = *wp;  wp += 128;
                    const float2 bb = *bp;  bp += 16;
                    float d0 = bb.x, d1 = bb.y, d2 = bb.x, d3 = bb.y;
                    mma_tf32(d0, d1, d2, d3, a00, a01, a02, a03,
                             __float_as_uint(bf.x), __float_as_uint(bf.y));
                    mma_tf32(d0, d1, d2, d3, a10, a11, a12, a13,
                             __float_as_uint(bf.z), __float_as_uint(bf.w));
                    d0 = fmaxf(d0, 0.0f); d1 = fmaxf(d1, 0.0f);
                    d2 = fmaxf(d2, 0.0f); d3 = fmaxf(d3, 0.0f);
                    acc[tsub] = fmaf(d0, m0.x, fmaf(d1, m0.y,
                                fmaf(d2, m1.x, fmaf(d3, m1.y, acc[tsub]))));
                }
            }
        }

        // Warp-reduce the 8 p-accumulators -> agg_sh[par][wq*8 + pi]
#pragma unroll
        for (int pi = 0; pi < 8; pi++) {
            float v = acc[pi];
#pragma unroll
            for (int o = 16; o; o >>= 1) v += __shfl_xor_sync(0xffffffffu, v, o);
            if (lane == 0) agg_sh[par * 32 + wq * 8 + pi] = v;
        }
        stream_bar(s);   // agg ready; E/mn free; tile_sh[next] visible
        it++;
    }

    // ---- Drain: GRU for the last processed tile ----
    if (wq == 3 && it > 0) {
        const int pp = (it - 1) & 1;
        gru_tile(tile_sh[pp], lane, x1_sh + pp * 32, agg_sh + pp * 32,
                 gi_sh, gh_sh, h1_sh, wihT, whhT, b_ih, b_hh, out);
    }
}

} // namespace

extern "C" void kernel_launch(void* const* d_in, const int* in_sizes, int n_in,
                              void* d_out, int out_size) {
    const float* nodes = (const float*)d_in[0];
    const float* edges = (const float*)d_in[1];
    const float* mask  = (const float*)d_in[2];
    const float* W_agg = (const float*)d_in[3];
    const float* b_agg = (const float*)d_in[4];
    const float* w_ih  = (const float*)d_in[5];
    const float* w_hh  = (const float*)d_in[6];
    const float* b_ih  = (const float*)d_in[7];
    const float* b_hh  = (const float*)d_in[8];
    float* out = (float*)d_out;

    void* ctr = nullptr;
    cudaGetSymbolAddress(&ctr, g_tile_counter);
    cudaMemsetAsync(ctr, 0, sizeof(int));

    cudaFuncSetAttribute(mp_layer_kernel,
                         cudaFuncAttributeMaxDynamicSharedMemorySize, SMEM_BYTES);
    mp_layer_kernel<<<GRID, THREADS, SMEM_BYTES>>>(nodes, edges, mask, W_agg, b_agg,
                                                   w_ih, w_hh, b_ih, b_hh, out);
}

// round 14
// speedup vs baseline: 1.0382x; 1.0382x over previous
#include <cuda_runtime.h>
#include <math.h>
#include <stdint.h>

__device__ int g_tile_counter;   // reset to 0 by kernel_launch each call

namespace {

constexpr int Bc = 32, Nc = 96, Dc = 32, Fc = 16;
constexpr int THREADS = 640;        // five independent 128-thread streams
constexpr int SWIDTH  = 128;
constexpr int NSTREAM = 5;
constexpr int GRID    = 152;        // persistent: 1 CTA per SM
constexpr int NTILES  = Bc * Nc;    // 3072
constexpr int NSTREAMS_TOTAL = GRID * NSTREAM;   // 760
constexpr int EPAD    = 20;

// Shared (read-only after init)
constexpr int OFF_WFRAG = 0;                 // float4[128 nt][32 lane] = 65536
constexpr int OFF_BIAS  = 65536;             // 1024 f = 4096
constexpr int OFF_WIH   = 69632;             // w_ih^T [32][96] = 12288
constexpr int OFF_WHH   = 81920;             // w_hh^T [32][96] = 12288
// Per-stream block
constexpr int OFF_S0  = 94208;
constexpr int SO_E    = 0;       // 96 x 20 u32 = 7680
constexpr int SO_MN   = 7680;    // 1536 float2 = 12288
constexpr int SO_ACT  = 19968;   // [2][96] int (parity double-buffer)
constexpr int SO_X1   = 20736;   // [2][32] f
constexpr int SO_META = 20992;   // cnt[2], tile[2]
constexpr int SO_AGG  = 21024;   // [2][32] f
constexpr int SO_GI   = 21280;   // 96 f
constexpr int SO_GH   = 21664;   // 96 f
constexpr int SO_H1   = 22048;   // 32 f
constexpr int S_BYTES = 22272;
constexpr int SMEM_BYTES = OFF_S0 + NSTREAM * S_BYTES;   // 205568

__device__ __forceinline__ float sigmoidf_(float x) { return 1.0f / (1.0f + expf(-x)); }

__device__ __forceinline__ uint32_t f2tf32(float x) {
    uint32_t r;
    asm("cvt.rna.tf32.f32 %0, %1;" : "=r"(r) : "f"(x));
    return r;
}

__device__ __forceinline__ void mma_tf32(float& d0, float& d1, float& d2, float& d3,
                                         uint32_t a0, uint32_t a1, uint32_t a2, uint32_t a3,
                                         uint32_t b0, uint32_t b1) {
    asm volatile(
        "mma.sync.aligned.m16n8k8.row.col.f32.tf32.tf32.f32 "
        "{%0,%1,%2,%3}, {%4,%5,%6,%7}, {%8,%9}, {%0,%1,%2,%3};"
        : "+f"(d0), "+f"(d1), "+f"(d2), "+f"(d3)
        : "r"(a0), "r"(a1), "r"(a2), "r"(a3), "r"(b0), "r"(b1));
}

// mn storage: (e,qp) -> float2 slot = ((qp>>2)*12 + (e>>3))*32 + (qp&3)*8 + (e&7)
__device__ __forceinline__ int mn_idx(int e, int qp) {
    return (((qp >> 2) * 12 + (e >> 3)) << 5) + ((qp & 3) << 3) + (e & 7);
}

__device__ __forceinline__ void stream_bar(int s) {
    asm volatile("bar.sync %0, %1;" :: "r"(s + 1), "r"(SWIDTH) : "memory");
}

// Warp-collective: compact active edges of tile t into slot p; stage x1.
__device__ __forceinline__ void compact_tile(int t, int p, int lane,
                                             const float* __restrict__ mask,
                                             const float* __restrict__ nodes,
                                             int* act_sh, int* cnt_sh, float* x1_sh) {
    const int b = t / Nc;
    const int i = t - b * Nc;
    const size_t mbase = (size_t)b * (Nc * Nc) + (size_t)i * Nc;
    int cnt = 0;
#pragma unroll
    for (int rr = 0; rr < Nc / 32; rr++) {
        const int j = rr * 32 + lane;
        const bool a = (mask[mbase + j] != 0.0f);
        const unsigned bal = __ballot_sync(0xffffffffu, a);
        if (a) act_sh[p * 96 + cnt + __popc(bal & ((1u << lane) - 1u))] = j;
        cnt += __popc(bal);
    }
    if (lane == 0) cnt_sh[p] = cnt;
    x1_sh[p * 32 + lane] = nodes[((size_t)b * Nc + i) * Dc + lane];
}

// Warp-collective GRU for one tile (warp 3 of each stream only).
__device__ __forceinline__ void gru_tile(int ptile, int lane,
                                         const float* x1p, const float* aggp,
                                         float* gi_sh, float* gh_sh, float* h1_sh,
                                         const float* wihT, const float* whhT,
                                         const float* __restrict__ b_ih,
                                         const float* __restrict__ b_hh,
                                         float* __restrict__ out) {
    const int pb = ptile / Nc;
    const int pi = ptile - pb * Nc;
#pragma unroll
    for (int g3 = 0; g3 < 3; g3++) {
        const int gate = g3 * 32 + lane;
        float g = b_ih[gate];
#pragma unroll
        for (int d = 0; d < Dc; d++) g = fmaf(x1p[d], wihT[d * 96 + gate], g);
        gi_sh[gate] = g;
    }
    __syncwarp();
    {
        const float r = sigmoidf_(gi_sh[lane] + b_hh[lane]);
        const float z = sigmoidf_(gi_sh[32 + lane] + b_hh[32 + lane]);
        const float n = tanhf(gi_sh[64 + lane] + r * b_hh[64 + lane]);
        h1_sh[lane] = (1.0f - z) * n;   // + z*h0, h0 = 0
    }
    __syncwarp();
#pragma unroll
    for (int g3 = 0; g3 < 3; g3++) {
        const int gate = g3 * 32 + lane;
        float g  = b_ih[gate];
        float gh = b_hh[gate];
#pragma unroll
        for (int d = 0; d < Dc; d++) {
            g  = fmaf(aggp[d],  wihT[d * 96 + gate], g);
            gh = fmaf(h1_sh[d], whhT[d * 96 + gate], gh);
        }
        gi_sh[gate] = g;
        gh_sh[gate] = gh;
    }
    __syncwarp();
    {
        const float r = sigmoidf_(gi_sh[lane] + gh_sh[lane]);
        const float z = sigmoidf_(gi_sh[32 + lane] + gh_sh[32 + lane]);
        const float n = tanhf(gi_sh[64 + lane] + r * gh_sh[64 + lane]);
        out[((size_t)pb * Nc + pi) * Dc + lane] = (1.0f - z) * n + z * h1_sh[lane];
    }
}

__global__ __launch_bounds__(THREADS, 1)
void mp_layer_kernel(const float* __restrict__ nodes,   // [B, N, D]
                     const float* __restrict__ edges,   // [B, N*N, F]
                     const float* __restrict__ mask,    // [B, N*N, 1] (0/1)
                     const float* __restrict__ W_agg,   // [F, D*D]
                     const float* __restrict__ b_agg,   // [D*D]
                     const float* __restrict__ w_ih,    // [3D, D]
                     const float* __restrict__ w_hh,    // [3D, D]
                     const float* __restrict__ b_ih,    // [3D]
                     const float* __restrict__ b_hh,    // [3D]
                     float* __restrict__ out)           // [B, N, D]
{
    extern __shared__ char smem[];
    float4* wfrag4  = reinterpret_cast<float4*>(smem + OFF_WFRAG);
    float*  bias_sh = reinterpret_cast<float*>(smem + OFF_BIAS);
    float*  wihT    = reinterpret_cast<float*>(smem + OFF_WIH);
    float*  whhT    = reinterpret_cast<float*>(smem + OFF_WHH);

    const int tid = threadIdx.x;

    // ---- One-time per CTA: W fragments (tf32, both k-steps packed), bias,
    //      transposed GRU weights ----
    for (int idx = tid; idx < 128 * 32; idx += THREADS) {
        const int l  = idx & 31;
        const int nt = idx >> 5;
        const int col = nt * 8 + (l >> 2);
        const int k   = l & 3;
        float4 v;
        v.x = __uint_as_float(f2tf32(W_agg[(k)      * 1024 + col]));
        v.y = __uint_as_float(f2tf32(W_agg[(k + 4)  * 1024 + col]));
        v.z = __uint_as_float(f2tf32(W_agg[(k + 8)  * 1024 + col]));
        v.w = __uint_as_float(f2tf32(W_agg[(k + 12) * 1024 + col]));
        wfrag4[idx] = v;
    }
    for (int c = tid; c < 1024; c += THREADS) bias_sh[c] = b_agg[c];
    for (int idx = tid; idx < 96 * 32; idx += THREADS) {
        const int g = idx >> 5;
        const int d = idx & 31;
        wihT[d * 96 + g] = w_ih[idx];
        whhT[d * 96 + g] = w_hh[idx];
    }
    __syncthreads();

    // ---- Stream-local views ----
    const int s    = tid >> 7;          // stream 0..4
    const int tids = tid & (SWIDTH - 1);
    const int lane = tid & 31;
    const int wq   = (tid >> 5) & 3;

    char* sbase = smem + OFF_S0 + s * S_BYTES;
    uint32_t* E_sh   = reinterpret_cast<uint32_t*>(sbase + SO_E);
    float2*   mnS    = reinterpret_cast<float2*>(sbase + SO_MN);
    int*      act_sh = reinterpret_cast<int*>(sbase + SO_ACT);
    float*    x1_sh  = reinterpret_cast<float*>(sbase + SO_X1);
    int*      cnt_sh = reinterpret_cast<int*>(sbase + SO_META);
    int*      tile_sh= reinterpret_cast<int*>(sbase + SO_META) + 2;
    float*    agg_sh = reinterpret_cast<float*>(sbase + SO_AGG);
    float*    gi_sh  = reinterpret_cast<float*>(sbase + SO_GI);
    float*    gh_sh  = reinterpret_cast<float*>(sbase + SO_GH);
    float*    h1_sh  = reinterpret_cast<float*>(sbase + SO_H1);

    const int gsid = blockIdx.x * NSTREAM + s;

    // ---- Prefetch: warp 3 compacts the stream's static first tile ----
    if (wq == 3) {
        if (lane == 0) tile_sh[0] = gsid;
        compact_tile(gsid, 0, lane, mask, nodes, act_sh, cnt_sh, x1_sh);
    }
    stream_bar(s);

    // Lane constants for the mainloop
    const int l4   = lane & 3;
    const int lr   = lane >> 2;
    const int mnlo = (l4 << 3) + (lr & 7);
    const int lrh  = lr >> 3;

    // ---- Dynamic pipelined tile loop ----
    int it = 0;
    while (true) {
        const int par = it & 1;
        const int cur = tile_sh[par];
        if (cur >= NTILES) break;                 // stream-uniform

        const int b = cur / Nc;
        const int i = cur - b * Nc;
        const size_t ebase = ((size_t)b * (Nc * Nc) + (size_t)i * Nc) * Fc;
        const size_t nbase = (size_t)b * (Nc * Dc);
        const int cnt    = cnt_sh[par];
        const int mtiles = (cnt + 15) >> 4;
        const int padcnt = mtiles << 4;

        if (wq < 3) {
            // Warps 0-2: stage E_act (tf32, float4-vectorized) and mn.
            const int* act = act_sh + par * 96;
            for (int idx = tids; idx < padcnt * 4; idx += 96) {
                const int a  = idx >> 2;
                const int f4 = (idx & 3) << 2;
                uint4 o = make_uint4(0u, 0u, 0u, 0u);
                if (a < cnt) {
                    const float4 v = *reinterpret_cast<const float4*>(
                        edges + ebase + (size_t)act[a] * Fc + f4);
                    o.x = f2tf32(v.x); o.y = f2tf32(v.y);
                    o.z = f2tf32(v.z); o.w = f2tf32(v.w);
                }
                *reinterpret_cast<uint4*>(E_sh + a * EPAD + f4) = o;
            }
            for (int idx = tids; idx < padcnt * 8; idx += 96) {
                const int a  = idx >> 3;
                const int q2 = (idx & 7) << 1;    // qp pair: q2, q2+1
                float4 v = make_float4(0.f, 0.f, 0.f, 0.f);
                if (a < cnt) {
                    v = *reinterpret_cast<const float4*>(
                        nodes + nbase + (size_t)act[a] * Dc + q2 * 2);
                }
                mnS[mn_idx(a, q2)]     = make_float2(v.x, v.y);
                mnS[mn_idx(a, q2 + 1)] = make_float2(v.z, v.w);
            }
        } else {
            // Warp 3: GRU(previous tile), then grab + compact next.
            if (it > 0) {
                const int pp = (it - 1) & 1;
                gru_tile(tile_sh[pp], lane, x1_sh + pp * 32, agg_sh + pp * 32,
                         gi_sh, gh_sh, h1_sh, wihT, whhT, b_ih, b_hh, out);
            }
            int nxt;
            if (lane == 0) nxt = NSTREAMS_TOTAL + atomicAdd(&g_tile_counter, 1);
            nxt = __shfl_sync(0xffffffffu, nxt, 0);
            const int np = (it + 1) & 1;
            if (lane == 0) tile_sh[np] = nxt;
            if (nxt < NTILES)
                compact_tile(nxt, np, lane, mask, nodes, act_sh, cnt_sh, x1_sh);
        }
        stream_bar(s);   // staging done, GRU done, next tile compacted

        // ---- MMA + fused epilogue (all 4 warps); PAIR-blocked m loop ----
        float acc[8] = {0.f, 0.f, 0.f, 0.f, 0.f, 0.f, 0.f, 0.f};

        int mt = 0;
        for (; mt + 2 <= mtiles; mt += 2) {
            const int r0 = mt * 16 + lr;
            const uint32_t* e0p = E_sh + r0 * EPAD;
            const uint32_t a00 = e0p[l4],            a01 = e0p[8*EPAD + l4];
            const uint32_t a02 = e0p[l4 + 4],        a03 = e0p[8*EPAD + l4 + 4];
            const uint32_t a10 = e0p[l4 + 8],        a11 = e0p[8*EPAD + l4 + 8];
            const uint32_t a12 = e0p[l4 + 12],       a13 = e0p[8*EPAD + l4 + 12];
            const uint32_t b00 = e0p[16*EPAD + l4],      b01 = e0p[24*EPAD + l4];
            const uint32_t b02 = e0p[16*EPAD + l4 + 4],  b03 = e0p[24*EPAD + l4 + 4];
            const uint32_t b10 = e0p[16*EPAD + l4 + 8],  b11 = e0p[24*EPAD + l4 + 8];
            const uint32_t b12 = e0p[16*EPAD + l4 + 12], b13 = e0p[24*EPAD + l4 + 12];
            const int blk0 = mt * 2 + lrh;

#pragma unroll
            for (int c = 0; c < 4; c++) {
                const float2* mp = mnS + ((c * 12 + blk0) << 5) + mnlo;
                const float2 m0 = mp[0];
                const float2 m1 = mp[32];
                const float2 m2 = mp[64];
                const float2 m3 = mp[96];
                const float4* wp = wfrag4 + (wq * 32 + c) * 32 + lane;
                const float2* bp = reinterpret_cast<const float2*>(
                    bias_sh + wq * 256 + c * 8 + l4 * 2);
#pragma unroll
                for (int tsub = 0; tsub < 8; tsub++) {
                    const float4 bf = *wp;  wp += 128;
                    const float2 bb = *bp;  bp += 16;
                    float d0 = bb.x, d1 = bb.y, d2 = bb.x, d3 = bb.y;
                    float f0 = bb.x, f1 = bb.y, f2 = bb.x, f3 = bb.y;
                    mma_tf32(d0, d1, d2, d3, a00, a01, a02, a03,
                             __float_as_uint(bf.x), __float_as_uint(bf.y));
                    mma_tf32(d0, d1, d2, d3, a10, a11, a12, a13,
                             __float_as_uint(bf.z), __float_as_uint(bf.w));
                    mma_tf32(f0, f1, f2, f3, b00, b01, b02, b03,
                             __float_as_uint(bf.x), __float_as_uint(bf.y));
                    mma_tf32(f0, f1, f2, f3, b10, b11, b12, b13,
                             __float_as_uint(bf.z), __float_as_uint(bf.w));
                    d0 = fmaxf(d0, 0.0f); d1 = fmaxf(d1, 0.0f);
                    d2 = fmaxf(d2, 0.0f); d3 = fmaxf(d3, 0.0f);
                    f0 = fmaxf(f0, 0.0f); f1 = fmaxf(f1, 0.0f);
                    f2 = fmaxf(f2, 0.0f); f3 = fmaxf(f3, 0.0f);
                    float v = fmaf(d0, m0.x, fmaf(d1, m0.y,
                              fmaf(d2, m1.x, fmaf(d3, m1.y, acc[tsub]))));
                    acc[tsub] = fmaf(f0, m2.x, fmaf(f1, m2.y,
                                fmaf(f2, m3.x, fmaf(f3, m3.y, v))));
                }
            }
        }
        if (mt < mtiles) {   // single-block tail (odd mtiles)
            const int r0 = mt * 16 + lr;
            const uint32_t* e0p = E_sh + r0 * EPAD;
            const uint32_t a00 = e0p[l4],      a01 = e0p[8*EPAD + l4];
            const uint32_t a02 = e0p[l4 + 4],  a03 = e0p[8*EPAD + l4 + 4];
            const uint32_t a10 = e0p[l4 + 8],  a11 = e0p[8*EPAD + l4 + 8];
            const uint32_t a12 = e0p[l4 + 12], a13 = e0p[8*EPAD + l4 + 12];
            const int blk0 = mt * 2 + lrh;
#pragma unroll
            for (int c = 0; c < 4; c++) {
                const float2* mp = mnS + ((c * 12 + blk0) << 5) + mnlo;
                const float2 m0 = mp[0];
                const float2 m1 = mp[32];
                const float4* wp = wfrag4 + (wq * 32 + c) * 32 + lane;
                const float2* bp = reinterpret_cast<const float2*>(
                    bias_sh + wq * 256 + c * 8 + l4 * 2);
#pragma unroll
                for (int tsub = 0; tsub < 8; tsub++) {
                    const float4 bf = *wp;  wp += 128;
                    const float2 bb = *bp;  bp += 16;
                    float d0 = bb.x, d1 = bb.y, d2 = bb.x, d3 = bb.y;
                    mma_tf32(d0, d1, d2, d3, a00, a01, a02, a03,
                             __float_as_uint(bf.x), __float_as_uint(bf.y));
                    mma_tf32(d0, d1, d2, d3, a10, a11, a12, a13,
                             __float_as_uint(bf.z), __float_as_uint(bf.w));
                    d0 = fmaxf(d0, 0.0f); d1 = fmaxf(d1, 0.0f);
                    d2 = fmaxf(d2, 0.0f); d3 = fmaxf(d3, 0.0f);
                    acc[tsub] = fmaf(d0, m0.x, fmaf(d1, m0.y,
                                fmaf(d2, m1.x, fmaf(d3, m1.y, acc[tsub]))));
                }
            }
        }

        // Warp-reduce the 8 p-accumulators -> agg_sh[par][wq*8 + pi]
#pragma unroll
        for (int pi = 0; pi < 8; pi++) {
            float v = acc[pi];
#pragma unroll
            for (int o = 16; o; o >>= 1) v += __shfl_xor_sync(0xffffffffu, v, o);
            if (lane == 0) agg_sh[par * 32 + wq * 8 + pi] = v;
        }
        stream_bar(s);   // agg ready; E/mn free; tile_sh[next] visible
        it++;
    }

    // ---- Drain: GRU for the last processed tile ----
    if (wq == 3 && it > 0) {
        const int pp = (it - 1) & 1;
        gru_tile(tile_sh[pp], lane, x1_sh + pp * 32, agg_sh + pp * 32,
                 gi_sh, gh_sh, h1_sh, wihT, whhT, b_ih, b_hh, out);
    }
}

} // namespace

extern "C" void kernel_launch(void* const* d_in, const int* in_sizes, int n_in,
                              void* d_out, int out_size) {
    const float* nodes = (const float*)d_in[0];
    const float* edges = (const float*)d_in[1];
    const float* mask  = (const float*)d_in[2];
    const float* W_agg = (const float*)d_in[3];
    const float* b_agg = (const float*)d_in[4];
    const float* w_ih  = (const float*)d_in[5];
    const float* w_hh  = (const float*)d_in[6];
    const float* b_ih  = (const float*)d_in[7];
    const float* b_hh  = (const float*)d_in[8];
    float* out = (float*)d_out;

    void* ctr = nullptr;
    cudaGetSymbolAddress(&ctr, g_tile_counter);
    cudaMemsetAsync(ctr, 0, sizeof(int));

    cudaFuncSetAttribute(mp_layer_kernel,
                         cudaFuncAttributeMaxDynamicSharedMemorySize, SMEM_BYTES);
    mp_layer_kernel<<<GRID, THREADS, SMEM_BYTES>>>(nodes, edges, mask, W_agg, b_agg,
                                                   w_ih, w_hh, b_ih, b_hh, out);
}